// round 6
// baseline (speedup 1.0000x reference)
#include <cuda_runtime.h>
#include <cuda_fp16.h>
#include <math.h>

#define Nn 8
#define Cc 256
#define Ll 512
#define Kk 100
#define ROWS (Nn * Ll)          // 4096
#define INV_TEMP 2.0f           // 1/0.5
#define EPS 1e-8f

// Scratch (no runtime allocation allowed)
__device__ __half g_zh[ROWS * Cc];     // z transposed + normalized, fp16 (2MB)
__device__ __half g_ch[ROWS * Cc];     // c transposed + normalized * INV_TEMP
__device__ float g_part[2 * ROWS * 4]; // per-(tensor,row) quarter sum-of-squares

// ---------------------------------------------------------------------------
// Norms from the ORIGINAL (N, C, cols) layout, wide loads along l.
// grid=256: [which(2)][n(8)][ltile128(4)][cquarter(4)], block=256 = 8 x 32.
// z path: lane loads float4 along l (512B/warp-instr). c path (stride 513,
// unaligned): 4 scalar loads. Each thread: 8 iterations over c.
// Block 0 thread 0 zeroes out[0].
// ---------------------------------------------------------------------------
__global__ void norms_k(const float* __restrict__ z, const float* __restrict__ c,
                        float* __restrict__ out)
{
    __shared__ float4 part4[8][32];

    int bb    = blockIdx.x;
    int cq    = bb & 3;
    int lt    = (bb >> 2) & 3;       // l-tile of 128
    int n     = (bb >> 4) & 7;
    int which = bb >> 7;

    if (bb == 0 && threadIdx.x == 0) out[0] = 0.0f;

    int g  = threadIdx.x & 31;
    int s  = threadIdx.x >> 5;
    int c0 = cq * 64 + s * 8;
    int l0 = lt * 128 + 4 * g;

    float4 acc = make_float4(0.f, 0.f, 0.f, 0.f);
    if (which == 0) {
        const float* src = z + (size_t)n * Cc * Ll + l0;
#pragma unroll
        for (int i = 0; i < 8; i++) {
            float4 v = *(const float4*)(src + (size_t)(c0 + i) * Ll);
            acc.x += v.x * v.x; acc.y += v.y * v.y;
            acc.z += v.z * v.z; acc.w += v.w * v.w;
        }
    } else {
        const float* src = c + (size_t)n * Cc * (Ll + 1) + 1 + l0;
#pragma unroll
        for (int i = 0; i < 8; i++) {
            const float* p = src + (size_t)(c0 + i) * (Ll + 1);
            float v0 = p[0], v1 = p[1], v2 = p[2], v3 = p[3];
            acc.x += v0 * v0; acc.y += v1 * v1;
            acc.z += v2 * v2; acc.w += v3 * v3;
        }
    }
    part4[s][g] = acc;
    __syncthreads();

    if (threadIdx.x < 128) {
        int t = threadIdx.x;                 // local l in [0,128)
        float sum = 0.f;
#pragma unroll
        for (int k = 0; k < 8; k++)
            sum += ((const float*)&part4[k][t >> 2])[t & 3];
        int row = n * Ll + lt * 128 + t;
        g_part[(which * ROWS + row) * 4 + cq] = sum;
    }
}

// ---------------------------------------------------------------------------
// Fused transpose + normalize + fp16 convert: (N, C, cols) -> (N*L, C) fp16.
// blockIdx.z: 0..7 -> z, 8..15 -> c (INV_TEMP folded). grid (16,8,16), (32,8).
// ---------------------------------------------------------------------------
__global__ void tscale_k(const float* __restrict__ z, const float* __restrict__ c)
{
    __shared__ float tile[32][33];
    __shared__ float inv_sh[32];

    int which = blockIdx.z >> 3;
    int n     = blockIdx.z & 7;
    int cols  = which ? (Ll + 1) : Ll;
    const float* in = which ? c : z;
    __half* out     = which ? g_ch : g_zh;

    int l0 = blockIdx.x * 32;
    int c0 = blockIdx.y * 32;
    int tx = threadIdx.x, ty = threadIdx.y;

    const float* src = in + (size_t)n * Cc * cols + (which ? 1 : 0);
#pragma unroll
    for (int i = 0; i < 32; i += 8)
        tile[ty + i][tx] = src[(size_t)(c0 + ty + i) * cols + l0 + tx];

    if (ty == 0) {
        int row = n * Ll + l0 + tx;
        const float* p = g_part + (size_t)(which * ROWS + row) * 4;
        float ssum = p[0] + p[1] + p[2] + p[3];
        float iv = 1.0f / fmaxf(sqrtf(ssum), EPS);
        if (which) iv *= INV_TEMP;
        inv_sh[tx] = iv;
    }
    __syncthreads();

    int rbase = n * Ll + l0;
#pragma unroll
    for (int i = 0; i < 32; i += 8)
        out[(size_t)(rbase + ty + i) * Cc + c0 + tx] =
            __float2half_rn(tile[tx][ty + i] * inv_sh[ty + i]);
}

// ---------------------------------------------------------------------------
// Main: one block per row, 128 threads = 8 half-warps. Half-warp h owns the
// contiguous dot chunk d in [13h, 13h+13) ∩ [0,101); d==0 is the positive,
// d>=1 -> negative inds[d-1]. Indices preloaded (1 ldg/lane) and broadcast
// via shfl. Unroll 2: four 128-bit gathers in flight before any FMA.
// ---------------------------------------------------------------------------
__global__ void logits_k(const int* __restrict__ neg_inds, float* __restrict__ out)
{
    __shared__ uint4 c_sh[32];
    __shared__ float logit_sh[Kk + 1];

    int row = blockIdx.x;
    int tid = threadIdx.x;
    int h   = tid >> 4;
    int hl  = tid & 15;
    unsigned hmask = 0xFFFFu << (tid & 16);

    if (tid < 32)
        c_sh[tid] = ((const uint4*)(g_ch + (size_t)row * Cc))[tid];

    // preload this half-warp's dot indices: lane hl holds j for d = 13h + hl
    int base = 13 * h;
    int jreg = row;
    {
        int d = base + hl;
        if (hl < 13 && d >= 1 && d < Kk + 1)
            jreg = __ldg(&neg_inds[(size_t)row * Kk + d - 1]);
    }
    __syncthreads();

    uint4 ca = c_sh[hl];
    uint4 cb = c_sh[16 + hl];
    __half2 cc0 = *(__half2*)&ca.x, cc1 = *(__half2*)&ca.y;
    __half2 cc2 = *(__half2*)&ca.z, cc3 = *(__half2*)&ca.w;
    __half2 cc4 = *(__half2*)&cb.x, cc5 = *(__half2*)&cb.y;
    __half2 cc6 = *(__half2*)&cb.z, cc7 = *(__half2*)&cb.w;

#define DOT(za, zb, sval) do {                                                \
        __half2 a0 = __float2half2_rn(0.f), a1 = __float2half2_rn(0.f);       \
        a0 = __hfma2(*(__half2*)&za.x, cc0, a0);                              \
        a0 = __hfma2(*(__half2*)&za.y, cc1, a0);                              \
        a0 = __hfma2(*(__half2*)&za.z, cc2, a0);                              \
        a0 = __hfma2(*(__half2*)&za.w, cc3, a0);                              \
        a1 = __hfma2(*(__half2*)&zb.x, cc4, a1);                              \
        a1 = __hfma2(*(__half2*)&zb.y, cc5, a1);                              \
        a1 = __hfma2(*(__half2*)&zb.z, cc6, a1);                              \
        a1 = __hfma2(*(__half2*)&zb.w, cc7, a1);                              \
        float2 f0 = __half22float2(a0);                                       \
        float2 f1 = __half22float2(a1);                                       \
        sval = (f0.x + f0.y) + (f1.x + f1.y);                                 \
    } while (0)

#pragma unroll 1
    for (int it = 0; it < 13; it += 2) {
        int d0 = base + it;
        int d1 = base + it + 1;
        int j0 = __shfl_sync(0xffffffffu, jreg, it, 16);
        int j1 = __shfl_sync(0xffffffffu, jreg, (it + 1 < 13) ? it + 1 : 12, 16);
        bool v0 = d0 < Kk + 1;
        bool v1 = (it + 1 < 13) && (d1 < Kk + 1);
        if (!v0) j0 = row;
        if (!v1) j1 = row;

        const uint4* zr0 = (const uint4*)(g_zh + (size_t)j0 * Cc);
        const uint4* zr1 = (const uint4*)(g_zh + (size_t)j1 * Cc);
        uint4 za0 = zr0[hl];
        uint4 zb0 = zr0[16 + hl];
        uint4 za1 = zr1[hl];
        uint4 zb1 = zr1[16 + hl];

        float s0, s1;
        DOT(za0, zb0, s0);
        DOT(za1, zb1, s1);
#pragma unroll
        for (int off = 8; off; off >>= 1) {
            s0 += __shfl_xor_sync(hmask, s0, off);
            s1 += __shfl_xor_sync(hmask, s1, off);
        }
        if (hl == 0) {
            if (v0) logit_sh[d0] = s0;
            if (v1) logit_sh[d1] = s1;
        }
    }
#undef DOT
    __syncthreads();

    if (tid < 32) {
        int lane = tid;
        float v0 = logit_sh[lane];
        float v1 = (lane + 32 < Kk + 1) ? logit_sh[lane + 32] : -INFINITY;
        float v2 = (lane + 64 < Kk + 1) ? logit_sh[lane + 64] : -INFINITY;
        float v3 = (lane + 96 < Kk + 1) ? logit_sh[lane + 96] : -INFINITY;
        float m = fmaxf(fmaxf(v0, v1), fmaxf(v2, v3));
#pragma unroll
        for (int off = 16; off; off >>= 1)
            m = fmaxf(m, __shfl_xor_sync(0xffffffffu, m, off));
        float e = __expf(v0 - m)
                + ((lane + 32 < Kk + 1) ? __expf(v1 - m) : 0.0f)
                + ((lane + 64 < Kk + 1) ? __expf(v2 - m) : 0.0f)
                + ((lane + 96 < Kk + 1) ? __expf(v3 - m) : 0.0f);
#pragma unroll
        for (int off = 16; off; off >>= 1)
            e += __shfl_xor_sync(0xffffffffu, e, off);
        if (lane == 0) {
            float item = m + logf(e) - logit_sh[0];
            atomicAdd(out, item * (1.0f / (float)ROWS));
        }
    }
}

extern "C" void kernel_launch(void* const* d_in, const int* in_sizes, int n_in,
                              void* d_out, int out_size)
{
    const float* z  = (const float*)d_in[0];   // (8, 256, 512)
    const float* c  = (const float*)d_in[1];   // (8, 256, 513)
    const int* inds = (const int*)d_in[2];     // (8, 512, 100)
    float* out = (float*)d_out;

    norms_k<<<256, 256>>>(z, c, out);

    dim3 tb(32, 8);
    dim3 tg(Ll / 32, Cc / 32, 2 * Nn);         // (16, 8, 16)
    tscale_k<<<tg, tb>>>(z, c);

    logits_k<<<ROWS, 128>>>(inds, out);
}